// round 12
// baseline (speedup 1.0000x reference)
#include <cuda_runtime.h>
#include <math.h>
#include <float.h>

#define BATCH 256
#define NCLS  1019          // C
#define GRID  7
#define NOBJ  16
#define NCH   1024          // 5 + C
#define PLANE 49            // G*G
#define BSTR  (NCH*PLANE)   // per-batch stride in floats
#define TPO   32            // threads per object (channel stripes)
#define NTHR  (TPO*NOBJ)    // 512 threads per block

// scratch for deterministic two-stage reduction (no cudaMalloc allowed)
__device__ double g_partials[BATCH];

__global__ void __launch_bounds__(NTHR, 2) yolo_main(
    const float* __restrict__ outputs,   // [B, 1024, 7, 7] f32
    const float* __restrict__ boxes,     // [B, 16, 4]      f32
    const int*   __restrict__ labels,    // [B, 16]         i32 (1..C)
    const int*   __restrict__ coords,    // [B, 16, 2]      i32 (x,y)
    const float* __restrict__ objm)      // [B, 49]         f32
{
    const int b   = blockIdx.x;
    const int tid = threadIdx.x;

    __shared__ int   s_cell[NOBJ];
    __shared__ float s_m[NTHR];
    __shared__ float s_s[NTHR];
    __shared__ float s_ce[NOBJ];
    __shared__ float s_obj;
    __shared__ float s_bbw[2];

    if (tid < NOBJ) {
        int x = coords[(b*NOBJ + tid)*2 + 0];
        int y = coords[(b*NOBJ + tid)*2 + 1];
        s_cell[tid] = y*GRID + x;
    }
    __syncthreads();

    // ---------------- class logsumexp (dominant work) ----------------
    // tid = t*16 + o : consecutive threads share channel t, differ in object o
    // -> each half-warp reads ONE 196B channel plane at 16 cell offsets (<=7 sectors).
    const int o = tid & (NOBJ - 1);
    const int t = tid >> 4;
    const float* __restrict__ base = outputs + (size_t)b*BSTR + 5*PLANE + s_cell[o];

    // delayed-rescale online logsumexp: ~1 expf per element (MUFU saver)
    float m = -FLT_MAX, s = 0.f;
    #pragma unroll 4
    for (int c = t; c < NCLS; c += TPO) {
        float v = __ldg(base + (size_t)c * PLANE);
        if (v <= m) {
            s += __expf(v - m);
        } else {
            s = s * __expf(m - v) + 1.0f;   // rare (~ln(32) times per thread)
            m = v;
        }
    }
    s_m[tid] = m;
    s_s[tid] = s;

    // ---------------- objectness CE (warp 0) ----------------
    if (tid < 32) {
        const float* p  = outputs + (size_t)b*BSTR;  // channel 0 plane
        const float* tm = objm + b*PLANE;
        bool  hi = (tid < PLANE - 32);               // tid+32 < 49
        float p0 = p[tid];
        float p1 = hi ? p[tid + 32] : -FLT_MAX;
        float t0 = tm[tid];
        float t1 = hi ? tm[tid + 32] : 0.0f;
        float mx = fmaxf(p0, p1);
        #pragma unroll
        for (int off = 16; off; off >>= 1)
            mx = fmaxf(mx, __shfl_xor_sync(0xffffffffu, mx, off));
        float se = expf(p0 - mx) + (hi ? expf(p1 - mx) : 0.0f);
        float dt = t0*p0 + t1*p1;     // t1=0, p1 finite -> term = -0.0, safe
        float st = t0 + t1;
        #pragma unroll
        for (int off = 16; off; off >>= 1) {
            se += __shfl_xor_sync(0xffffffffu, se, off);
            dt += __shfl_xor_sync(0xffffffffu, dt, off);
            st += __shfl_xor_sync(0xffffffffu, st, off);
        }
        if (tid == 0) s_obj = st * (mx + logf(se)) - dt;
    }
    // ---------------- bbox L2 (warps 2,3) ----------------
    else if (tid >= 64 && tid < 128) {
        int   i   = tid - 64;               // 0..63
        int   oo  = i >> 2, j = i & 3;
        float pred = outputs[(size_t)b*BSTR + (size_t)(1 + j)*PLANE + s_cell[oo]];
        float tv   = boxes[(b*NOBJ + oo)*4 + j];
        float tgt  = rintf(tv / 448.0f * 10.0f) / 10.0f;  // jnp.round = half-to-even = rintf
        float d    = tgt - pred;
        float v    = d * d;
        #pragma unroll
        for (int off = 16; off; off >>= 1)
            v += __shfl_xor_sync(0xffffffffu, v, off);
        if ((i & 31) == 0) s_bbw[i >> 5] = v;
    }
    __syncthreads();

    // ---------------- per-object combine (threads 0..15) ----------------
    if (tid < NOBJ) {
        float M = -FLT_MAX;
        #pragma unroll
        for (int k = 0; k < TPO; k++) M = fmaxf(M, s_m[k*NOBJ + tid]);
        float S = 0.0f;
        #pragma unroll
        for (int k = 0; k < TPO; k++) S += s_s[k*NOBJ + tid] * __expf(s_m[k*NOBJ + tid] - M);
        int   lab    = labels[b*NOBJ + tid] - 1;   // 0..C-1
        float picked = outputs[(size_t)b*BSTR + (size_t)(5 + lab)*PLANE + s_cell[tid]];
        s_ce[tid] = (M + logf(S)) - picked;
    }
    __syncthreads();

    if (tid == 0) {
        double acc = (double)s_obj + (double)s_bbw[0] + (double)s_bbw[1];
        #pragma unroll
        for (int k = 0; k < NOBJ; k++) acc += (double)s_ce[k];
        g_partials[b] = acc;
    }
}

__global__ void yolo_reduce(float* __restrict__ out) {
    __shared__ double sh[BATCH];
    int tid = threadIdx.x;
    sh[tid] = g_partials[tid];
    __syncthreads();
    #pragma unroll
    for (int off = BATCH/2; off > 0; off >>= 1) {
        if (tid < off) sh[tid] += sh[tid + off];
        __syncthreads();
    }
    if (tid == 0) out[0] = (float)(sh[0] / (double)BATCH);
}

extern "C" void kernel_launch(void* const* d_in, const int* in_sizes, int n_in,
                              void* d_out, int out_size) {
    const float* outputs = (const float*)d_in[0];
    const float* boxes   = (const float*)d_in[1];
    const int*   labels  = (const int*)  d_in[2];
    const int*   coords  = (const int*)  d_in[3];
    const float* objm    = (const float*)d_in[4];

    yolo_main<<<BATCH, NTHR>>>(outputs, boxes, labels, coords, objm);
    yolo_reduce<<<1, BATCH>>>((float*)d_out);
}

// round 13
// speedup vs baseline: 1.0021x; 1.0021x over previous
#include <cuda_runtime.h>
#include <math.h>
#include <float.h>

#define BATCH 256
#define NCLS  1019          // C
#define GRID  7
#define NOBJ  16
#define NCH   1024          // 5 + C
#define PLANE 49            // G*G
#define BSTR  (NCH*PLANE)   // per-batch stride in floats
#define TPO   32            // threads per object (channel stripes)
#define NTHR  (TPO*NOBJ)    // 512 threads per block

// scratch for deterministic two-stage reduction (no cudaMalloc allowed)
__device__ double g_partials[BATCH];

__global__ void __launch_bounds__(NTHR, 2) yolo_main(
    const float* __restrict__ outputs,   // [B, 1024, 7, 7] f32
    const float* __restrict__ boxes,     // [B, 16, 4]      f32
    const int*   __restrict__ labels,    // [B, 16]         i32 (1..C)
    const int*   __restrict__ coords,    // [B, 16, 2]      i32 (x,y)
    const float* __restrict__ objm)      // [B, 49]         f32
{
    const int b   = blockIdx.x;
    const int tid = threadIdx.x;

    __shared__ int   s_cell[NOBJ];
    __shared__ float s_m[NTHR];
    __shared__ float s_s[NTHR];
    __shared__ float s_ce[NOBJ];
    __shared__ float s_obj;
    __shared__ float s_bbw[2];

    if (tid < NOBJ) {
        int x = coords[(b*NOBJ + tid)*2 + 0];
        int y = coords[(b*NOBJ + tid)*2 + 1];
        s_cell[tid] = y*GRID + x;
    }
    __syncthreads();

    // ---------------- class logsumexp (dominant work) ----------------
    // tid = t*16 + o : consecutive threads share channel t, differ in object o
    // -> each half-warp reads ONE 196B channel plane at 16 cell offsets (<=7 sectors).
    const int o = tid & (NOBJ - 1);
    const int t = tid >> 4;
    const float* __restrict__ base = outputs + (size_t)b*BSTR + 5*PLANE + s_cell[o];

    // delayed-rescale online logsumexp: ~1 expf per element (MUFU saver)
    float m = -FLT_MAX, s = 0.f;
    #pragma unroll 4
    for (int c = t; c < NCLS; c += TPO) {
        float v = __ldg(base + (size_t)c * PLANE);
        if (v <= m) {
            s += __expf(v - m);
        } else {
            s = s * __expf(m - v) + 1.0f;   // rare (~ln(32) times per thread)
            m = v;
        }
    }
    s_m[tid] = m;
    s_s[tid] = s;

    // ---------------- objectness CE (warp 0) ----------------
    if (tid < 32) {
        const float* p  = outputs + (size_t)b*BSTR;  // channel 0 plane
        const float* tm = objm + b*PLANE;
        bool  hi = (tid < PLANE - 32);               // tid+32 < 49
        float p0 = p[tid];
        float p1 = hi ? p[tid + 32] : -FLT_MAX;
        float t0 = tm[tid];
        float t1 = hi ? tm[tid + 32] : 0.0f;
        float mx = fmaxf(p0, p1);
        #pragma unroll
        for (int off = 16; off; off >>= 1)
            mx = fmaxf(mx, __shfl_xor_sync(0xffffffffu, mx, off));
        float se = expf(p0 - mx) + (hi ? expf(p1 - mx) : 0.0f);
        float dt = t0*p0 + t1*p1;     // t1=0, p1 finite -> term = -0.0, safe
        float st = t0 + t1;
        #pragma unroll
        for (int off = 16; off; off >>= 1) {
            se += __shfl_xor_sync(0xffffffffu, se, off);
            dt += __shfl_xor_sync(0xffffffffu, dt, off);
            st += __shfl_xor_sync(0xffffffffu, st, off);
        }
        if (tid == 0) s_obj = st * (mx + logf(se)) - dt;
    }
    // ---------------- bbox L2 (warps 2,3) ----------------
    else if (tid >= 64 && tid < 128) {
        int   i   = tid - 64;               // 0..63
        int   oo  = i >> 2, j = i & 3;
        float pred = outputs[(size_t)b*BSTR + (size_t)(1 + j)*PLANE + s_cell[oo]];
        float tv   = boxes[(b*NOBJ + oo)*4 + j];
        float tgt  = rintf(tv / 448.0f * 10.0f) / 10.0f;  // jnp.round = half-to-even = rintf
        float d    = tgt - pred;
        float v    = d * d;
        #pragma unroll
        for (int off = 16; off; off >>= 1)
            v += __shfl_xor_sync(0xffffffffu, v, off);
        if ((i & 31) == 0) s_bbw[i >> 5] = v;
    }
    __syncthreads();

    // ---------------- per-object combine (threads 0..15) ----------------
    if (tid < NOBJ) {
        float M = -FLT_MAX;
        #pragma unroll
        for (int k = 0; k < TPO; k++) M = fmaxf(M, s_m[k*NOBJ + tid]);
        float S = 0.0f;
        #pragma unroll
        for (int k = 0; k < TPO; k++) S += s_s[k*NOBJ + tid] * __expf(s_m[k*NOBJ + tid] - M);
        int   lab    = labels[b*NOBJ + tid] - 1;   // 0..C-1
        float picked = outputs[(size_t)b*BSTR + (size_t)(5 + lab)*PLANE + s_cell[tid]];
        s_ce[tid] = (M + logf(S)) - picked;
    }
    __syncthreads();

    if (tid == 0) {
        double acc = (double)s_obj + (double)s_bbw[0] + (double)s_bbw[1];
        #pragma unroll
        for (int k = 0; k < NOBJ; k++) acc += (double)s_ce[k];
        g_partials[b] = acc;
    }
}

__global__ void yolo_reduce(float* __restrict__ out) {
    __shared__ double sh[BATCH];
    int tid = threadIdx.x;
    sh[tid] = g_partials[tid];
    __syncthreads();
    #pragma unroll
    for (int off = BATCH/2; off > 0; off >>= 1) {
        if (tid < off) sh[tid] += sh[tid + off];
        __syncthreads();
    }
    if (tid == 0) out[0] = (float)(sh[0] / (double)BATCH);
}

extern "C" void kernel_launch(void* const* d_in, const int* in_sizes, int n_in,
                              void* d_out, int out_size) {
    const float* outputs = (const float*)d_in[0];
    const float* boxes   = (const float*)d_in[1];
    const int*   labels  = (const int*)  d_in[2];
    const int*   coords  = (const int*)  d_in[3];
    const float* objm    = (const float*)d_in[4];

    yolo_main<<<BATCH, NTHR>>>(outputs, boxes, labels, coords, objm);
    yolo_reduce<<<1, BATCH>>>((float*)d_out);
}

// round 14
// speedup vs baseline: 1.0042x; 1.0021x over previous
#include <cuda_runtime.h>
#include <math.h>
#include <float.h>

#define BATCH 256
#define NCLS  1019          // C
#define GRID  7
#define NOBJ  16
#define NCH   1024          // 5 + C
#define PLANE 49            // G*G
#define BSTR  (NCH*PLANE)   // per-batch stride in floats
#define TPO   32            // threads per object (channel stripes)
#define NTHR  (TPO*NOBJ)    // 512 threads per block

// scratch for deterministic single-kernel reduction (no cudaMalloc allowed)
__device__ double       g_partials[BATCH];
__device__ unsigned int g_done = 0;   // reset to 0 by last block each launch

__global__ void __launch_bounds__(NTHR, 2) yolo_main(
    const float* __restrict__ outputs,   // [B, 1024, 7, 7] f32
    const float* __restrict__ boxes,     // [B, 16, 4]      f32
    const int*   __restrict__ labels,    // [B, 16]         i32 (1..C)
    const int*   __restrict__ coords,    // [B, 16, 2]      i32 (x,y)
    const float* __restrict__ objm,      // [B, 49]         f32
    float*       __restrict__ out)       // [1]             f32
{
    const int b   = blockIdx.x;
    const int tid = threadIdx.x;

    __shared__ int   s_cell[NOBJ];
    __shared__ float s_m[NTHR];
    __shared__ float s_s[NTHR];
    __shared__ float s_ce[NOBJ];
    __shared__ float s_obj;
    __shared__ float s_bbw[2];
    __shared__ int   s_last;

    if (tid < NOBJ) {
        int x = coords[(b*NOBJ + tid)*2 + 0];
        int y = coords[(b*NOBJ + tid)*2 + 1];
        s_cell[tid] = y*GRID + x;
    }
    __syncthreads();

    // ---------------- class logsumexp (dominant work) ----------------
    // tid = t*16 + o : consecutive threads share channel t, differ in object o
    // -> each half-warp reads ONE 196B channel plane at 16 cell offsets (<=7 sectors).
    const int o = tid & (NOBJ - 1);
    const int t = tid >> 4;
    const float* __restrict__ base = outputs + (size_t)b*BSTR + 5*PLANE + s_cell[o];

    // delayed-rescale online logsumexp: ~1 expf per element (MUFU saver)
    float m = -FLT_MAX, s = 0.f;
    #pragma unroll 4
    for (int c = t; c < NCLS; c += TPO) {
        float v = __ldg(base + (size_t)c * PLANE);
        if (v <= m) {
            s += __expf(v - m);
        } else {
            s = s * __expf(m - v) + 1.0f;   // rare (~ln(32) times per thread)
            m = v;
        }
    }
    s_m[tid] = m;
    s_s[tid] = s;

    // ---------------- objectness CE (warp 0) ----------------
    if (tid < 32) {
        const float* p  = outputs + (size_t)b*BSTR;  // channel 0 plane
        const float* tm = objm + b*PLANE;
        bool  hi = (tid < PLANE - 32);               // tid+32 < 49
        float p0 = p[tid];
        float p1 = hi ? p[tid + 32] : -FLT_MAX;
        float t0 = tm[tid];
        float t1 = hi ? tm[tid + 32] : 0.0f;
        float mx = fmaxf(p0, p1);
        #pragma unroll
        for (int off = 16; off; off >>= 1)
            mx = fmaxf(mx, __shfl_xor_sync(0xffffffffu, mx, off));
        float se = expf(p0 - mx) + (hi ? expf(p1 - mx) : 0.0f);
        float dt = t0*p0 + t1*p1;     // t1=0, p1 finite -> term = -0.0, safe
        float st = t0 + t1;
        #pragma unroll
        for (int off = 16; off; off >>= 1) {
            se += __shfl_xor_sync(0xffffffffu, se, off);
            dt += __shfl_xor_sync(0xffffffffu, dt, off);
            st += __shfl_xor_sync(0xffffffffu, st, off);
        }
        if (tid == 0) s_obj = st * (mx + logf(se)) - dt;
    }
    // ---------------- bbox L2 (warps 2,3) ----------------
    else if (tid >= 64 && tid < 128) {
        int   i   = tid - 64;               // 0..63
        int   oo  = i >> 2, j = i & 3;
        float pred = outputs[(size_t)b*BSTR + (size_t)(1 + j)*PLANE + s_cell[oo]];
        float tv   = boxes[(b*NOBJ + oo)*4 + j];
        float tgt  = rintf(tv / 448.0f * 10.0f) / 10.0f;  // jnp.round = half-to-even = rintf
        float d    = tgt - pred;
        float v    = d * d;
        #pragma unroll
        for (int off = 16; off; off >>= 1)
            v += __shfl_xor_sync(0xffffffffu, v, off);
        if ((i & 31) == 0) s_bbw[i >> 5] = v;
    }
    __syncthreads();

    // ---------------- per-object combine (threads 0..15) ----------------
    if (tid < NOBJ) {
        float M = -FLT_MAX;
        #pragma unroll
        for (int k = 0; k < TPO; k++) M = fmaxf(M, s_m[k*NOBJ + tid]);
        float S = 0.0f;
        #pragma unroll
        for (int k = 0; k < TPO; k++) S += s_s[k*NOBJ + tid] * __expf(s_m[k*NOBJ + tid] - M);
        int   lab    = labels[b*NOBJ + tid] - 1;   // 0..C-1
        float picked = outputs[(size_t)b*BSTR + (size_t)(5 + lab)*PLANE + s_cell[tid]];
        s_ce[tid] = (M + logf(S)) - picked;
    }
    __syncthreads();

    // ---------------- publish partial + last-block detection ----------------
    if (tid == 0) {
        double acc = (double)s_obj + (double)s_bbw[0] + (double)s_bbw[1];
        #pragma unroll
        for (int k = 0; k < NOBJ; k++) acc += (double)s_ce[k];
        g_partials[b] = acc;
        __threadfence();                       // make partial visible before count
        unsigned v = atomicAdd(&g_done, 1u);
        s_last = (v == BATCH - 1u);
    }
    __syncthreads();

    // ---------------- final reduction in the last-arriving block ----------------
    if (s_last) {
        __threadfence();                       // acquire all partials
        __shared__ double sh[BATCH];
        if (tid < BATCH)
            sh[tid] = ((volatile double*)g_partials)[tid];
        __syncthreads();
        // fixed-order tree reduce -> bit-deterministic output across replays
        #pragma unroll
        for (int off = BATCH/2; off > 0; off >>= 1) {
            if (tid < off) sh[tid] += sh[tid + off];
            __syncthreads();
        }
        if (tid == 0) {
            out[0]  = (float)(sh[0] / (double)BATCH);
            g_done = 0;                        // reset for next graph replay
        }
    }
}

extern "C" void kernel_launch(void* const* d_in, const int* in_sizes, int n_in,
                              void* d_out, int out_size) {
    const float* outputs = (const float*)d_in[0];
    const float* boxes   = (const float*)d_in[1];
    const int*   labels  = (const int*)  d_in[2];
    const int*   coords  = (const int*)  d_in[3];
    const float* objm    = (const float*)d_in[4];

    yolo_main<<<BATCH, NTHR>>>(outputs, boxes, labels, coords, objm, (float*)d_out);
}

// round 15
// speedup vs baseline: 1.1766x; 1.1716x over previous
#include <cuda_runtime.h>
#include <math.h>
#include <float.h>

#define BATCH 256
#define NCLS  1019          // C
#define GRID  7
#define NOBJ  16
#define NCH   1024          // 5 + C
#define PLANE 49            // G*G
#define BSTR  (NCH*PLANE)   // per-batch stride in floats
#define OBJ_PB 8            // objects per block (batch split in 2)
#define NTHR  256           // 32 channel-stripes x 8 objects
#define NBLK  (BATCH*2)     // 512 blocks

// scratch for deterministic single-kernel reduction (no cudaMalloc allowed)
__device__ double       g_partials[NBLK];
__device__ unsigned int g_done = 0;   // reset to 0 by last block each launch

// combine two (m, s) logsumexp partials, branch-free
__device__ __forceinline__ void lse_merge(float& m, float& s, float m2, float s2) {
    float nm = fmaxf(m, m2);
    s = s * __expf(m - nm) + s2 * __expf(m2 - nm);
    m = nm;
}

__global__ void __launch_bounds__(NTHR) yolo_main(
    const float* __restrict__ outputs,   // [B, 1024, 7, 7] f32
    const float* __restrict__ boxes,     // [B, 16, 4]      f32
    const int*   __restrict__ labels,    // [B, 16]         i32 (1..C)
    const int*   __restrict__ coords,    // [B, 16, 2]      i32 (x,y)
    const float* __restrict__ objm,      // [B, 49]         f32
    float*       __restrict__ out)       // [1]             f32
{
    const int bid  = blockIdx.x;
    const int b    = bid >> 1;
    const int half = bid & 1;            // which 8 objects of the batch
    const int tid  = threadIdx.x;

    __shared__ int    s_cell[OBJ_PB];
    __shared__ float  s_m2[64], s_s2[64];   // per-(warp, object) partials
    __shared__ float  s_ce[OBJ_PB];
    __shared__ float  s_obj;
    __shared__ float  s_bb;
    __shared__ int    s_last;
    __shared__ double sh[NBLK];             // final reduce (last block only)

    if (tid < OBJ_PB) {
        int oo = half*OBJ_PB + tid;
        int x = coords[(b*NOBJ + oo)*2 + 0];
        int y = coords[(b*NOBJ + oo)*2 + 1];
        s_cell[tid] = y*GRID + x;
    }
    __syncthreads();

    // ---------------- class logsumexp (dominant, DRAM-streaming) ----------------
    // tid = t*8 + o : a warp reads 4 channel planes at 8 cell offsets -> few lines/LDG.
    const int o = tid & (OBJ_PB - 1);
    const int t = tid >> 3;              // 0..31 channel stripe
    const float* __restrict__ base = outputs + (size_t)b*BSTR + 5*PLANE + s_cell[o];

    // branch-free online logsumexp: straight-line, loads front-batch under unroll
    float m = -FLT_MAX, s = 0.f;
    #pragma unroll 4
    for (int c = t; c < NCLS; c += 32) {
        float v  = __ldg(base + (size_t)c * PLANE);
        float nm = fmaxf(m, v);
        s = s * __expf(m - nm) + __expf(v - nm);
        m = nm;
    }
    // in-warp combine of the 4 channel stripes sharing this object (xor 8, 16)
    {
        float m2 = __shfl_xor_sync(0xffffffffu, m, 8);
        float s2 = __shfl_xor_sync(0xffffffffu, s, 8);
        lse_merge(m, s, m2, s2);
        m2 = __shfl_xor_sync(0xffffffffu, m, 16);
        s2 = __shfl_xor_sync(0xffffffffu, s, 16);
        lse_merge(m, s, m2, s2);
    }
    {
        int lane = tid & 31, w = tid >> 5;
        if (lane < OBJ_PB) { s_m2[w*OBJ_PB + lane] = m; s_s2[w*OBJ_PB + lane] = s; }
    }

    // ---------------- bbox L2 for this block's 8 objects (warp 1) ----------------
    if (tid >= 32 && tid < 64) {
        int   i    = tid - 32;               // 0..31
        int   oo   = i >> 2, j = i & 3;
        float pred = outputs[(size_t)b*BSTR + (size_t)(1 + j)*PLANE + s_cell[oo]];
        float tv   = boxes[(b*NOBJ + half*OBJ_PB + oo)*4 + j];
        float tgt  = rintf(tv / 448.0f * 10.0f) / 10.0f;  // jnp.round = half-to-even
        float d    = tgt - pred;
        float v    = d * d;
        #pragma unroll
        for (int off = 16; off; off >>= 1)
            v += __shfl_xor_sync(0xffffffffu, v, off);
        if (i == 0) s_bb = v;
    }
    // ---------------- objectness CE (warp 2, half==0 blocks only) ----------------
    else if (half == 0 && tid >= 64 && tid < 96) {
        int lane = tid - 64;
        const float* p  = outputs + (size_t)b*BSTR;  // channel 0 plane
        const float* tm = objm + b*PLANE;
        bool  hi = (lane < PLANE - 32);              // lane+32 < 49
        float p0 = p[lane];
        float p1 = hi ? p[lane + 32] : -FLT_MAX;
        float t0 = tm[lane];
        float t1 = hi ? tm[lane + 32] : 0.0f;
        float mx = fmaxf(p0, p1);
        #pragma unroll
        for (int off = 16; off; off >>= 1)
            mx = fmaxf(mx, __shfl_xor_sync(0xffffffffu, mx, off));
        float se = expf(p0 - mx) + (hi ? expf(p1 - mx) : 0.0f);
        float dt = t0*p0 + t1*p1;
        float st = t0 + t1;
        #pragma unroll
        for (int off = 16; off; off >>= 1) {
            se += __shfl_xor_sync(0xffffffffu, se, off);
            dt += __shfl_xor_sync(0xffffffffu, dt, off);
            st += __shfl_xor_sync(0xffffffffu, st, off);
        }
        if (lane == 0) s_obj = st * (mx + logf(se)) - dt;
    }
    __syncthreads();

    // ---------------- per-object combine (threads 0..7) ----------------
    if (tid < OBJ_PB) {
        float M = -FLT_MAX;
        #pragma unroll
        for (int w = 0; w < 8; w++) M = fmaxf(M, s_m2[w*OBJ_PB + tid]);
        float S = 0.0f;
        #pragma unroll
        for (int w = 0; w < 8; w++) S += s_s2[w*OBJ_PB + tid] * __expf(s_m2[w*OBJ_PB + tid] - M);
        int   lab    = labels[b*NOBJ + half*OBJ_PB + tid] - 1;   // 0..C-1
        float picked = outputs[(size_t)b*BSTR + (size_t)(5 + lab)*PLANE + s_cell[tid]];
        s_ce[tid] = (M + logf(S)) - picked;
    }
    __syncthreads();

    // ---------------- publish partial + last-block detection ----------------
    if (tid == 0) {
        double acc = (double)s_bb + (half == 0 ? (double)s_obj : 0.0);
        #pragma unroll
        for (int k = 0; k < OBJ_PB; k++) acc += (double)s_ce[k];
        g_partials[bid] = acc;
        __threadfence();
        unsigned v = atomicAdd(&g_done, 1u);
        s_last = (v == NBLK - 1u);
    }
    __syncthreads();

    // ---------------- final fixed-order reduction in the last block ----------------
    if (s_last) {
        __threadfence();
        volatile double* gp = g_partials;
        sh[tid] = gp[tid] + gp[tid + NTHR];
        __syncthreads();
        #pragma unroll
        for (int off = NTHR/2; off > 0; off >>= 1) {
            if (tid < off) sh[tid] += sh[tid + off];
            __syncthreads();
        }
        if (tid == 0) {
            out[0] = (float)(sh[0] / (double)BATCH);
            g_done = 0;                        // reset for next graph replay
        }
    }
}

extern "C" void kernel_launch(void* const* d_in, const int* in_sizes, int n_in,
                              void* d_out, int out_size) {
    const float* outputs = (const float*)d_in[0];
    const float* boxes   = (const float*)d_in[1];
    const int*   labels  = (const int*)  d_in[2];
    const int*   coords  = (const int*)  d_in[3];
    const float* objm    = (const float*)d_in[4];

    yolo_main<<<NBLK, NTHR>>>(outputs, boxes, labels, coords, objm, (float*)d_out);
}